// round 2
// baseline (speedup 1.0000x reference)
#include <cuda_runtime.h>
#include <cstdint>

// Problem constants (B=2, H=16, S=2048, D=128, fp32 in/out, int32 mask over keys)
constexpr int Bc = 2, Hh = 16, Ss = 2048, Dd = 128;
constexpr int BM = 64;          // queries per block
constexpr int BN = 64;          // keys per KV tile
constexpr int NTHREADS = 128;   // 4 warps, one per SMSP
constexpr int KSTRIDE = 132;    // smem row stride (words) for K  -> conflict-free LDS
constexpr int VSTRIDE = 136;    // smem row stride (words) for V  -> conflict-free LDS
constexpr float SCALE_F = 0.08838834764831845f;  // 1/sqrt(128)
constexpr float NEGF = -1000000000.0f;

// fp32 -> tf32 (round to nearest)
__device__ __forceinline__ uint32_t f2tf(float x) {
    uint32_t r;
    asm("cvt.rna.tf32.f32 %0, %1;" : "=r"(r) : "f"(x));
    return r;
}

// D(16x8,f32) += A(16x8,tf32,row) * B(8x8,tf32,col)
__device__ __forceinline__ void mma8(float* d, uint32_t a0, uint32_t a1, uint32_t a2,
                                     uint32_t a3, uint32_t b0, uint32_t b1) {
    asm volatile(
        "mma.sync.aligned.m16n8k8.row.col.f32.tf32.tf32.f32 "
        "{%0,%1,%2,%3},{%4,%5,%6,%7},{%8,%9},{%0,%1,%2,%3};"
        : "+f"(d[0]), "+f"(d[1]), "+f"(d[2]), "+f"(d[3])
        : "r"(a0), "r"(a1), "r"(a2), "r"(a3), "r"(b0), "r"(b1));
}

__global__ void __launch_bounds__(NTHREADS, 1)
fa_tf32_kernel(const float* __restrict__ q, const float* __restrict__ k,
               const float* __restrict__ v, const int* __restrict__ mask,
               float* __restrict__ out) {
    extern __shared__ uint32_t smem[];
    uint32_t* sK = smem;                              // 64*132 words (tf32)
    uint32_t* sV = smem + BN * KSTRIDE;               // 64*136 words (tf32)
    float* sMask = (float*)(smem + BN * KSTRIDE + BN * VSTRIDE);  // 2048 words

    const int tid = threadIdx.x;
    const int warp = tid >> 5, lane = tid & 31;
    const int g = lane >> 2, tig = lane & 3;          // groupID, thread-in-group
    const int qb = blockIdx.x, bh = blockIdx.y;
    const int b = bh / Hh;

    const size_t bh_base = (size_t)bh * Ss * Dd;
    const float* qg = q + bh_base + (size_t)qb * BM * Dd;
    const float* kg = k + bh_base;
    const float* vg = v + bh_base;

    // Stage mask row for this batch (selector 1.0 / 0.0), once per block.
    for (int i = tid; i < Ss; i += NTHREADS)
        sMask[i] = (mask[b * Ss + i] != 0) ? 1.0f : 0.0f;

    // Stage Q (raw fp32) into the sK region, then pull A-fragments to registers.
    float* sQ = (float*)sK;
    for (int i = tid; i < BM * (Dd / 4); i += NTHREADS) {
        int r = i >> 5, c = (i & 31) * 4;
        float4 t4 = *(const float4*)(qg + (size_t)r * Dd + c);
        *(float4*)(sQ + r * KSTRIDE + c) = t4;
    }
    __syncthreads();

    const int r0 = warp * 16 + g;   // query row (within block) for acc rows 0/1
    const int r1 = r0 + 8;          // query row for acc rows 2/3

    uint32_t qf[16][4];             // Q A-fragments for all 16 k-steps (D=128)
#pragma unroll
    for (int kk = 0; kk < 16; kk++) {
        qf[kk][0] = f2tf(sQ[r0 * KSTRIDE + kk * 8 + tig]);
        qf[kk][1] = f2tf(sQ[r1 * KSTRIDE + kk * 8 + tig]);
        qf[kk][2] = f2tf(sQ[r0 * KSTRIDE + kk * 8 + tig + 4]);
        qf[kk][3] = f2tf(sQ[r1 * KSTRIDE + kk * 8 + tig + 4]);
    }

    float oa[16][4];                // O accumulator: 16 n-tiles x (2 rows x 2 cols)
#pragma unroll
    for (int n = 0; n < 16; n++)
        oa[n][0] = oa[n][1] = oa[n][2] = oa[n][3] = 0.f;
    float m0 = -1e30f, m1 = -1e30f, l0 = 0.f, l1 = 0.f;

#pragma unroll 1
    for (int t = 0; t < Ss / BN; t++) {
        const int n0 = t * BN;
        __syncthreads();  // all warps done with previous sK/sV (and Q extraction)

        // Stage K and V tiles as tf32 into padded smem.
        for (int i = tid; i < BN * (Dd / 4); i += NTHREADS) {
            int r = i >> 5, c = (i & 31) * 4;
            float4 t4 = *(const float4*)(kg + (size_t)(n0 + r) * Dd + c);
            uint4 u;
            u.x = f2tf(t4.x); u.y = f2tf(t4.y); u.z = f2tf(t4.z); u.w = f2tf(t4.w);
            *(uint4*)(sK + r * KSTRIDE + c) = u;
            float4 t5 = *(const float4*)(vg + (size_t)(n0 + r) * Dd + c);
            uint4 w;
            w.x = f2tf(t5.x); w.y = f2tf(t5.y); w.z = f2tf(t5.z); w.w = f2tf(t5.w);
            *(uint4*)(sV + r * VSTRIDE + c) = w;
        }
        __syncthreads();

        // ---- S = Q K^T (16 x 64 per warp) ----
        float sa[8][4];
#pragma unroll
        for (int j = 0; j < 8; j++)
            sa[j][0] = sa[j][1] = sa[j][2] = sa[j][3] = 0.f;
#pragma unroll
        for (int kk = 0; kk < 16; kk++) {
#pragma unroll
            for (int j = 0; j < 8; j++) {
                uint32_t b0 = sK[(j * 8 + g) * KSTRIDE + kk * 8 + tig];
                uint32_t b1 = sK[(j * 8 + g) * KSTRIDE + kk * 8 + tig + 4];
                mma8(sa[j], qf[kk][0], qf[kk][1], qf[kk][2], qf[kk][3], b0, b1);
            }
        }

        // ---- mask + scale + row max ----
        float mx0 = -1e30f, mx1 = -1e30f;
#pragma unroll
        for (int j = 0; j < 8; j++) {
            float sel0 = sMask[n0 + j * 8 + 2 * tig];
            float sel1 = sMask[n0 + j * 8 + 2 * tig + 1];
            sa[j][0] = (sel0 != 0.f) ? sa[j][0] * SCALE_F : NEGF;
            sa[j][1] = (sel1 != 0.f) ? sa[j][1] * SCALE_F : NEGF;
            sa[j][2] = (sel0 != 0.f) ? sa[j][2] * SCALE_F : NEGF;
            sa[j][3] = (sel1 != 0.f) ? sa[j][3] * SCALE_F : NEGF;
            mx0 = fmaxf(mx0, fmaxf(sa[j][0], sa[j][1]));
            mx1 = fmaxf(mx1, fmaxf(sa[j][2], sa[j][3]));
        }
        mx0 = fmaxf(mx0, __shfl_xor_sync(0xffffffffu, mx0, 1));
        mx0 = fmaxf(mx0, __shfl_xor_sync(0xffffffffu, mx0, 2));
        mx1 = fmaxf(mx1, __shfl_xor_sync(0xffffffffu, mx1, 1));
        mx1 = fmaxf(mx1, __shfl_xor_sync(0xffffffffu, mx1, 2));

        float mn0 = fmaxf(m0, mx0), mn1 = fmaxf(m1, mx1);
        float al0 = __expf(m0 - mn0), al1 = __expf(m1 - mn1);

        // ---- P = exp(S - m), row sums; store P back as tf32 bits in sa ----
        float rs0 = 0.f, rs1 = 0.f;
#pragma unroll
        for (int j = 0; j < 8; j++) {
            float p00 = __expf(sa[j][0] - mn0);
            float p01 = __expf(sa[j][1] - mn0);
            float p10 = __expf(sa[j][2] - mn1);
            float p11 = __expf(sa[j][3] - mn1);
            rs0 += p00 + p01;
            rs1 += p10 + p11;
            sa[j][0] = __uint_as_float(f2tf(p00));
            sa[j][1] = __uint_as_float(f2tf(p01));
            sa[j][2] = __uint_as_float(f2tf(p10));
            sa[j][3] = __uint_as_float(f2tf(p11));
        }
        rs0 += __shfl_xor_sync(0xffffffffu, rs0, 1);
        rs0 += __shfl_xor_sync(0xffffffffu, rs0, 2);
        rs1 += __shfl_xor_sync(0xffffffffu, rs1, 1);
        rs1 += __shfl_xor_sync(0xffffffffu, rs1, 2);
        l0 = l0 * al0 + rs0;
        l1 = l1 * al1 + rs1;
        m0 = mn0;
        m1 = mn1;

        // rescale O accumulator
#pragma unroll
        for (int n = 0; n < 16; n++) {
            oa[n][0] *= al0; oa[n][1] *= al0;
            oa[n][2] *= al1; oa[n][3] *= al1;
        }

        // ---- O += P V : convert P acc-layout -> A-fragment layout via shfl ----
#pragma unroll
        for (int kk = 0; kk < 8; kk++) {
            uint32_t c0 = __float_as_uint(sa[kk][0]);
            uint32_t c1 = __float_as_uint(sa[kk][1]);
            uint32_t c2 = __float_as_uint(sa[kk][2]);
            uint32_t c3 = __float_as_uint(sa[kk][3]);
            int src0 = (lane & 28) | (tig >> 1);  // col tig lives at t' = tig/2
            int src1 = src0 + 2;                  // col tig+4 lives at t' = tig/2+2
            uint32_t x0 = __shfl_sync(0xffffffffu, c0, src0);
            uint32_t x1 = __shfl_sync(0xffffffffu, c1, src0);
            uint32_t y0 = __shfl_sync(0xffffffffu, c0, src1);
            uint32_t y1 = __shfl_sync(0xffffffffu, c1, src1);
            uint32_t a0 = (tig & 1) ? x1 : x0;    // P[g][8kk+tig]
            uint32_t a2 = (tig & 1) ? y1 : y0;    // P[g][8kk+tig+4]
            x0 = __shfl_sync(0xffffffffu, c2, src0);
            x1 = __shfl_sync(0xffffffffu, c3, src0);
            y0 = __shfl_sync(0xffffffffu, c2, src1);
            y1 = __shfl_sync(0xffffffffu, c3, src1);
            uint32_t a1 = (tig & 1) ? x1 : x0;    // P[g+8][8kk+tig]
            uint32_t a3 = (tig & 1) ? y1 : y0;    // P[g+8][8kk+tig+4]
#pragma unroll
            for (int n = 0; n < 16; n++) {
                uint32_t b0 = sV[(kk * 8 + tig) * VSTRIDE + n * 8 + g];
                uint32_t b1 = sV[(kk * 8 + tig + 4) * VSTRIDE + n * 8 + g];
                mma8(oa[n], a0, a1, a2, a3, b0, b1);
            }
        }
    }

    // ---- epilogue: normalize and store ----
    float i0 = 1.f / l0, i1 = 1.f / l1;
    float* og = out + bh_base + (size_t)qb * BM * Dd;
#pragma unroll
    for (int n = 0; n < 16; n++) {
        int c = n * 8 + 2 * tig;
        float2 v0 = make_float2(oa[n][0] * i0, oa[n][1] * i0);
        float2 v1 = make_float2(oa[n][2] * i1, oa[n][3] * i1);
        *(float2*)(og + (size_t)r0 * Dd + c) = v0;
        *(float2*)(og + (size_t)r1 * Dd + c) = v1;
    }
}

extern "C" void kernel_launch(void* const* d_in, const int* in_sizes, int n_in,
                              void* d_out, int out_size) {
    (void)in_sizes; (void)n_in; (void)out_size;
    const float* q = (const float*)d_in[0];
    const float* k = (const float*)d_in[1];
    const float* v = (const float*)d_in[2];
    const int* mask = (const int*)d_in[3];
    float* out = (float*)d_out;

    constexpr int SMEM_BYTES = (BN * KSTRIDE + BN * VSTRIDE + Ss) * 4;  // 76800
    cudaFuncSetAttribute(fa_tf32_kernel, cudaFuncAttributeMaxDynamicSharedMemorySize,
                         SMEM_BYTES);
    dim3 grid(Ss / BM, Bc * Hh);
    fa_tf32_kernel<<<grid, NTHREADS, SMEM_BYTES>>>(q, k, v, mask, out);
}

// round 3
// speedup vs baseline: 1.1005x; 1.1005x over previous
#include <cuda_runtime.h>
#include <cstdint>

// Problem: B=2, H=16, S=2048, D=128, fp32 in/out, int32 mask over keys.
constexpr int Bc = 2, Hh = 16, Ss = 2048, Dd = 128;
constexpr int BM = 128;         // queries per block (8 warps x 16 rows)
constexpr int BN = 64;          // keys per KV tile
constexpr int NT = 256;         // threads
constexpr int KST = 66;         // K^T smem row stride (words): 64 + 2  (==2 mod 32 -> LDS.64 conflict-free)
constexpr int VST = 132;        // V smem row stride (words): 128 + 4   (==4 mod 32 -> LDS.128 conflict-free)
constexpr int NTILES = Ss / BN; // 32
constexpr float SCALE_F = 0.08838834764831845f;  // 1/sqrt(128)

// Pre-converted tf32 K (transposed + seq-permuted) and V (col-permuted).
// g_ktp layout: [bh][c][t*64 + perm(r)],  perm(r) = (r%8)*8 + r/8 (involution)
// g_vtp layout: [bh][r][(c%8)*16 + c/8]
__device__ __align__(16) float g_ktp[(size_t)Bc * Hh * Dd * Ss];
__device__ __align__(16) float g_vtp[(size_t)Bc * Hh * Ss * Dd];

__device__ __forceinline__ uint32_t f2tf(float x) {
    uint32_t r;
    asm("cvt.rna.tf32.f32 %0, %1;" : "=r"(r) : "f"(x));
    return r;
}

__device__ __forceinline__ void mma8(float* d, uint32_t a0, uint32_t a1, uint32_t a2,
                                     uint32_t a3, uint32_t b0, uint32_t b1) {
    asm volatile(
        "mma.sync.aligned.m16n8k8.row.col.f32.tf32.tf32.f32 "
        "{%0,%1,%2,%3},{%4,%5,%6,%7},{%8,%9},{%0,%1,%2,%3};"
        : "+f"(d[0]), "+f"(d[1]), "+f"(d[2]), "+f"(d[3])
        : "r"(a0), "r"(a1), "r"(a2), "r"(a3), "r"(b0), "r"(b1));
}

__device__ __forceinline__ void cp16(uint32_t dst, const void* src) {
    asm volatile("cp.async.ca.shared.global [%0], [%1], 16;" :: "r"(dst), "l"(src));
}
__device__ __forceinline__ void cp8(uint32_t dst, const void* src) {
    asm volatile("cp.async.ca.shared.global [%0], [%1], 8;" :: "r"(dst), "l"(src));
}

// ---------------- pre-pass: tf32 convert + layout transform ----------------
__global__ void __launch_bounds__(256) prep_kernel(const float* __restrict__ k,
                                                   const float* __restrict__ v) {
    __shared__ float sk[64 * 129];
    const int t = blockIdx.x, bh = blockIdx.y, tid = threadIdx.x;
    const float* kg = k + ((size_t)bh * Ss + (size_t)t * 64) * Dd;
    const float* vg = v + ((size_t)bh * Ss + (size_t)t * 64) * Dd;

    // stage K tile (64 seq x 128 d), coalesced
    for (int i = tid; i < 64 * 32; i += 256) {
        int r = i >> 5, c4 = (i & 31) << 2;
        float4 x = *(const float4*)(kg + (size_t)r * Dd + c4);
        sk[r * 129 + c4 + 0] = x.x;
        sk[r * 129 + c4 + 1] = x.y;
        sk[r * 129 + c4 + 2] = x.z;
        sk[r * 129 + c4 + 3] = x.w;
    }
    __syncthreads();

    // K^T with seq-perm, coalesced writes over p
    float* kt = g_ktp + (size_t)bh * Dd * Ss + (size_t)t * 64;
    for (int i = tid; i < Dd * 64; i += 256) {
        int c = i >> 6, p = i & 63;
        int pr = ((p & 7) << 3) | (p >> 3);   // perm (involution)
        kt[(size_t)c * Ss + p] = __uint_as_float(f2tf(sk[pr * 129 + c]));
    }

    // V row-major with col-perm (writes stay within each 512B row)
    float* vt = g_vtp + ((size_t)bh * Ss + (size_t)t * 64) * Dd;
    for (int i = tid; i < 64 * 32; i += 256) {
        int r = i >> 5, c4 = (i & 31) << 2;
        float4 x = *(const float4*)(vg + (size_t)r * Dd + c4);
        float a[4] = {x.x, x.y, x.z, x.w};
#pragma unroll
        for (int u = 0; u < 4; u++) {
            int c = c4 + u;
            vt[(size_t)r * Dd + ((c & 7) << 4) + (c >> 3)] = __uint_as_float(f2tf(a[u]));
        }
    }
}

// ---------------- main kernel ----------------
// smem words: sK[2][128*66]=16896 | sV[2][64*132]=16896 | mask 2048  => 35840 w = 140KB
__global__ void __launch_bounds__(NT, 1)
fa_kernel(const float* __restrict__ q, const int* __restrict__ mask,
          float* __restrict__ out) {
    extern __shared__ uint32_t sm[];
    uint32_t* sKb[2] = {sm, sm + 8448};
    uint32_t* sVb[2] = {sm + 16896, sm + 25344};
    float* sMask = (float*)(sm + 33792);

    const int tid = threadIdx.x, warp = tid >> 5, lane = tid & 31;
    const int g = lane >> 2, tig = lane & 3;
    const int qb = blockIdx.x, bh = blockIdx.y, b = bh >> 4;  // Hh=16
    const size_t bh_base = (size_t)bh * Ss * Dd;

    for (int i = tid; i < Ss; i += NT)
        sMask[i] = mask[b * Ss + i] ? 1.0f : 0.0f;

    // stage Q through the K smem region, build pre-scaled tf32 A-fragments
    float* sQ = (float*)sm;
    const float* qg = q + bh_base + (size_t)qb * BM * Dd;
    for (int i = tid; i < BM * 32; i += NT) {
        int r = i >> 5, c = (i & 31) << 2;
        *(float4*)(sQ + r * 132 + c) = *(const float4*)(qg + (size_t)r * Dd + c);
    }
    __syncthreads();
    const int r0 = warp * 16 + g, r1 = r0 + 8;
    uint32_t qf[16][4];
#pragma unroll
    for (int kk = 0; kk < 16; kk++) {
        qf[kk][0] = f2tf(sQ[r0 * 132 + kk * 8 + tig] * SCALE_F);
        qf[kk][1] = f2tf(sQ[r1 * 132 + kk * 8 + tig] * SCALE_F);
        qf[kk][2] = f2tf(sQ[r0 * 132 + kk * 8 + tig + 4] * SCALE_F);
        qf[kk][3] = f2tf(sQ[r1 * 132 + kk * 8 + tig + 4] * SCALE_F);
    }
    __syncthreads();

    const uint32_t sbase = (uint32_t)__cvta_generic_to_shared(sm);
    const uint32_t kaddr[2] = {sbase, sbase + 8448u * 4u};
    const uint32_t vaddr[2] = {sbase + 16896u * 4u, sbase + 25344u * 4u};
    const float* ktsrc = g_ktp + (size_t)bh * Dd * Ss;
    const float* vtsrc = g_vtp + (size_t)bh * Ss * Dd;

    auto issue_tile = [&](int t, int bi) {
        const float* ks = ktsrc + (size_t)t * 64;
        const float* vs = vtsrc + (size_t)t * 64 * Dd;
        uint32_t kb = kaddr[bi], vb = vaddr[bi];
#pragma unroll
        for (int i = 0; i < 16; i++) {          // K: 4096 8B-chunks (stride 66 kills 16B align)
            int ch = tid + i * NT;
            int c = ch >> 5, po = (ch & 31) << 1;
            cp8(kb + (uint32_t)(c * KST + po) * 4u, ks + (size_t)c * Ss + po);
        }
#pragma unroll
        for (int i = 0; i < 8; i++) {           // V: 2048 16B-chunks
            int ch = tid + i * NT;
            int r = ch >> 5, po = (ch & 31) << 2;
            cp16(vb + (uint32_t)(r * VST + po) * 4u, vs + (size_t)r * Dd + po);
        }
        asm volatile("cp.async.commit_group;" ::: "memory");
    };

    float oa[16][4];
#pragma unroll
    for (int n = 0; n < 16; n++)
        oa[n][0] = oa[n][1] = oa[n][2] = oa[n][3] = 0.f;
    float l0 = 0.f, l1 = 0.f;

    issue_tile(0, 0);

#pragma unroll 1
    for (int t = 0; t < NTILES; t++) {
        const int bi = t & 1;
        if (t + 1 < NTILES) {
            issue_tile(t + 1, bi ^ 1);
            asm volatile("cp.async.wait_group 1;" ::: "memory");
        } else {
            asm volatile("cp.async.wait_group 0;" ::: "memory");
        }
        __syncthreads();
        const uint32_t* Kb = sKb[bi];
        const uint32_t* Vb = sVb[bi];

        // ---- S = (Q*scale) K^T : conflict-free LDS.64 fragments ----
        float sa[8][4];
#pragma unroll
        for (int j = 0; j < 8; j++)
            sa[j][0] = sa[j][1] = sa[j][2] = sa[j][3] = 0.f;
#pragma unroll
        for (int kk = 0; kk < 16; kk++) {
            const uint32_t* kr0 = Kb + (kk * 8 + tig) * KST + g * 8;
            const uint32_t* kr1 = kr0 + 4 * KST;
            uint2 u0 = *(const uint2*)(kr0 + 0), u1 = *(const uint2*)(kr0 + 2);
            uint2 u2 = *(const uint2*)(kr0 + 4), u3 = *(const uint2*)(kr0 + 6);
            uint2 w0 = *(const uint2*)(kr1 + 0), w1 = *(const uint2*)(kr1 + 2);
            uint2 w2 = *(const uint2*)(kr1 + 4), w3 = *(const uint2*)(kr1 + 6);
            mma8(sa[0], qf[kk][0], qf[kk][1], qf[kk][2], qf[kk][3], u0.x, w0.x);
            mma8(sa[1], qf[kk][0], qf[kk][1], qf[kk][2], qf[kk][3], u0.y, w0.y);
            mma8(sa[2], qf[kk][0], qf[kk][1], qf[kk][2], qf[kk][3], u1.x, w1.x);
            mma8(sa[3], qf[kk][0], qf[kk][1], qf[kk][2], qf[kk][3], u1.y, w1.y);
            mma8(sa[4], qf[kk][0], qf[kk][1], qf[kk][2], qf[kk][3], u2.x, w2.x);
            mma8(sa[5], qf[kk][0], qf[kk][1], qf[kk][2], qf[kk][3], u2.y, w2.y);
            mma8(sa[6], qf[kk][0], qf[kk][1], qf[kk][2], qf[kk][3], u3.x, w3.x);
            mma8(sa[7], qf[kk][0], qf[kk][1], qf[kk][2], qf[kk][3], u3.y, w3.y);
        }

        // ---- p = exp(s) * mask_sel  (softmax shift-invariance: no running max) ----
        const int n0 = t * BN;
#pragma unroll
        for (int j = 0; j < 8; j++) {
            float2 ms = *(const float2*)(sMask + n0 + j * 8 + 2 * tig);
            float p00 = __expf(sa[j][0]) * ms.x;
            float p01 = __expf(sa[j][1]) * ms.y;
            float p10 = __expf(sa[j][2]) * ms.x;
            float p11 = __expf(sa[j][3]) * ms.y;
            l0 += p00 + p01;
            l1 += p10 + p11;
            sa[j][0] = __uint_as_float(f2tf(p00));
            sa[j][1] = __uint_as_float(f2tf(p01));
            sa[j][2] = __uint_as_float(f2tf(p10));
            sa[j][3] = __uint_as_float(f2tf(p11));
        }

        // ---- O += P V : shfl layout conversion + conflict-free LDS.128 V frags ----
#pragma unroll
        for (int kk = 0; kk < 8; kk++) {
            uint32_t c0 = __float_as_uint(sa[kk][0]);
            uint32_t c1 = __float_as_uint(sa[kk][1]);
            uint32_t c2 = __float_as_uint(sa[kk][2]);
            uint32_t c3 = __float_as_uint(sa[kk][3]);
            int src0 = (lane & 28) | (tig >> 1);
            int src1 = src0 + 2;
            uint32_t x0 = __shfl_sync(0xffffffffu, c0, src0);
            uint32_t x1 = __shfl_sync(0xffffffffu, c1, src0);
            uint32_t y0 = __shfl_sync(0xffffffffu, c0, src1);
            uint32_t y1 = __shfl_sync(0xffffffffu, c1, src1);
            uint32_t a0 = (tig & 1) ? x1 : x0;
            uint32_t a2 = (tig & 1) ? y1 : y0;
            x0 = __shfl_sync(0xffffffffu, c2, src0);
            x1 = __shfl_sync(0xffffffffu, c3, src0);
            y0 = __shfl_sync(0xffffffffu, c2, src1);
            y1 = __shfl_sync(0xffffffffu, c3, src1);
            uint32_t a1 = (tig & 1) ? x1 : x0;
            uint32_t a3 = (tig & 1) ? y1 : y0;

            const uint32_t* vr0 = Vb + (kk * 8 + tig) * VST + g * 16;
            const uint32_t* vr1 = vr0 + 4 * VST;
            uint4 v0 = *(const uint4*)(vr0 + 0), v1 = *(const uint4*)(vr0 + 4);
            uint4 v2 = *(const uint4*)(vr0 + 8), v3 = *(const uint4*)(vr0 + 12);
            uint4 z0 = *(const uint4*)(vr1 + 0), z1 = *(const uint4*)(vr1 + 4);
            uint4 z2 = *(const uint4*)(vr1 + 8), z3 = *(const uint4*)(vr1 + 12);
            mma8(oa[0],  a0, a1, a2, a3, v0.x, z0.x);
            mma8(oa[1],  a0, a1, a2, a3, v0.y, z0.y);
            mma8(oa[2],  a0, a1, a2, a3, v0.z, z0.z);
            mma8(oa[3],  a0, a1, a2, a3, v0.w, z0.w);
            mma8(oa[4],  a0, a1, a2, a3, v1.x, z1.x);
            mma8(oa[5],  a0, a1, a2, a3, v1.y, z1.y);
            mma8(oa[6],  a0, a1, a2, a3, v1.z, z1.z);
            mma8(oa[7],  a0, a1, a2, a3, v1.w, z1.w);
            mma8(oa[8],  a0, a1, a2, a3, v2.x, z2.x);
            mma8(oa[9],  a0, a1, a2, a3, v2.y, z2.y);
            mma8(oa[10], a0, a1, a2, a3, v2.z, z2.z);
            mma8(oa[11], a0, a1, a2, a3, v2.w, z2.w);
            mma8(oa[12], a0, a1, a2, a3, v3.x, z3.x);
            mma8(oa[13], a0, a1, a2, a3, v3.y, z3.y);
            mma8(oa[14], a0, a1, a2, a3, v3.z, z3.z);
            mma8(oa[15], a0, a1, a2, a3, v3.w, z3.w);
        }
        __syncthreads();  // compute done before buffer bi gets re-issued
    }

    // ---- epilogue: reduce l over the 4-thread group, normalize, store ----
    l0 += __shfl_xor_sync(0xffffffffu, l0, 1);
    l0 += __shfl_xor_sync(0xffffffffu, l0, 2);
    l1 += __shfl_xor_sync(0xffffffffu, l1, 1);
    l1 += __shfl_xor_sync(0xffffffffu, l1, 2);
    float i0 = 1.f / l0, i1 = 1.f / l1;
    float* og = out + bh_base + (size_t)qb * BM * Dd;
#pragma unroll
    for (int n = 0; n < 16; n++) {
        int c = n * 8 + 2 * tig;
        *(float2*)(og + (size_t)r0 * Dd + c) = make_float2(oa[n][0] * i0, oa[n][1] * i0);
        *(float2*)(og + (size_t)r1 * Dd + c) = make_float2(oa[n][2] * i1, oa[n][3] * i1);
    }
}

extern "C" void kernel_launch(void* const* d_in, const int* in_sizes, int n_in,
                              void* d_out, int out_size) {
    (void)in_sizes; (void)n_in; (void)out_size;
    const float* q = (const float*)d_in[0];
    const float* k = (const float*)d_in[1];
    const float* v = (const float*)d_in[2];
    const int* mask = (const int*)d_in[3];
    float* out = (float*)d_out;

    prep_kernel<<<dim3(Ss / 64, Bc * Hh), 256>>>(k, v);

    constexpr int SMEM_BYTES = 35840 * 4;  // 143,360
    cudaFuncSetAttribute(fa_kernel, cudaFuncAttributeMaxDynamicSharedMemorySize,
                         SMEM_BYTES);
    fa_kernel<<<dim3(Ss / BM, Bc * Hh), NT, SMEM_BYTES>>>(q, mask, out);
}

// round 5
// speedup vs baseline: 2.0143x; 1.8304x over previous
#include <cuda_runtime.h>
#include <cstdint>

// Problem: B=2, H=16, S=2048, D=128, fp32 in/out, int32 mask over keys.
// Key fact exploited: masked keys (mask==0, ~50%) contribute exactly zero to
// softmax; mask is per (b,s). We compact K/V to unmasked keys once, then run
// the flash loop over ~half the tiles.
constexpr int Bc = 2, Hh = 16, Ss = 2048, Dd = 128;
constexpr int BM = 128;         // queries per block (8 warps x 16 rows)
constexpr int NT = 256;         // threads
constexpr int KST = 66;         // K^T smem row stride (words) -> LDS.64 conflict-free
constexpr int VST = 132;        // V smem row stride (words)  -> LDS.128 conflict-free
constexpr float SCALE_F = 0.08838834764831845f;  // 1/sqrt(128)

// Compaction tables
__device__ int g_cnt[Bc];              // padded unmasked count (multiple of 64)
__device__ int g_idx[Bc][Ss];          // compacted source key indices
__device__ float g_sel[Bc][Ss];        // 1.0 real key / 0.0 padding
// Pre-converted tf32 K (transposed + seq-permuted) and V (col-permuted), compacted.
// g_ktp layout: [bh][c][j]  (j = compact position, perm within each 64-tile)
// g_vtp layout: [bh][j][(c%8)*16 + c/8]
__device__ __align__(16) float g_ktp[(size_t)Bc * Hh * Dd * Ss];
__device__ __align__(16) float g_vtp[(size_t)Bc * Hh * Ss * Dd];

__device__ __forceinline__ uint32_t f2tf(float x) {
    uint32_t r;
    asm("cvt.rna.tf32.f32 %0, %1;" : "=r"(r) : "f"(x));
    return r;
}

__device__ __forceinline__ void mma8(float* d, uint32_t a0, uint32_t a1, uint32_t a2,
                                     uint32_t a3, uint32_t b0, uint32_t b1) {
    asm volatile(
        "mma.sync.aligned.m16n8k8.row.col.f32.tf32.tf32.f32 "
        "{%0,%1,%2,%3},{%4,%5,%6,%7},{%8,%9},{%0,%1,%2,%3};"
        : "+f"(d[0]), "+f"(d[1]), "+f"(d[2]), "+f"(d[3])
        : "r"(a0), "r"(a1), "r"(a2), "r"(a3), "r"(b0), "r"(b1));
}

__device__ __forceinline__ void cp16(uint32_t dst, const void* src) {
    asm volatile("cp.async.ca.shared.global [%0], [%1], 16;" :: "r"(dst), "l"(src));
}
__device__ __forceinline__ void cp8(uint32_t dst, const void* src) {
    asm volatile("cp.async.ca.shared.global [%0], [%1], 8;" :: "r"(dst), "l"(src));
}

// ---------------- pass 1: compact unmasked key indices (one block per batch) ----
__global__ void __launch_bounds__(256) compact_kernel(const int* __restrict__ mask) {
    __shared__ int wcnt[64], woff[64];
    __shared__ int s_tot[2];
    const int b = blockIdx.x, tid = threadIdx.x;
    const int warp = tid >> 5, lane = tid & 31;

    for (int ch = warp; ch < 64; ch += 8) {
        int m = mask[b * Ss + ch * 32 + lane] != 0;
        unsigned bal = __ballot_sync(0xffffffffu, m);
        if (lane == 0) wcnt[ch] = __popc(bal);
    }
    __syncthreads();
    if (tid == 0) {
        int s = 0;
        for (int i = 0; i < 64; i++) { woff[i] = s; s += wcnt[i]; }
        int pad = (s + 63) & ~63;
        g_cnt[b] = pad;
        s_tot[0] = s;
        s_tot[1] = pad;
    }
    __syncthreads();
    const int total = s_tot[0], pad = s_tot[1];
    for (int ch = warp; ch < 64; ch += 8) {
        int src = ch * 32 + lane;
        int m = mask[b * Ss + src] != 0;
        unsigned bal = __ballot_sync(0xffffffffu, m);
        if (m) {
            int pos = woff[ch] + __popc(bal & ((1u << lane) - 1u));
            g_idx[b][pos] = src;
            g_sel[b][pos] = 1.0f;
        }
    }
    __syncthreads();
    for (int i = total + tid; i < pad; i += 256) {  // padding -> key 0, sel 0
        g_idx[b][i] = 0;
        g_sel[b][i] = 0.0f;
    }
}

// ---------------- pass 2: gather + tf32 convert + layout transform ----------------
__global__ void __launch_bounds__(256) prep_kernel(const float* __restrict__ k,
                                                   const float* __restrict__ v) {
    __shared__ float sk[64 * 129];
    __shared__ int sidx[64];
    const int t = blockIdx.x, bh = blockIdx.y, tid = threadIdx.x;
    const int b = bh >> 4;
    if (t * 64 >= g_cnt[b]) return;
    const int base = t * 64;
    const float* kg = k + (size_t)bh * Ss * Dd;
    const float* vg = v + (size_t)bh * Ss * Dd;

    if (tid < 64) sidx[tid] = g_idx[b][base + tid];
    __syncthreads();

    // gather K rows into smem (coalesced within each row)
    for (int i = tid; i < 64 * 32; i += 256) {
        int r = i >> 5, c4 = (i & 31) << 2;
        float4 x = *(const float4*)(kg + (size_t)sidx[r] * Dd + c4);
        sk[r * 129 + c4 + 0] = x.x;
        sk[r * 129 + c4 + 1] = x.y;
        sk[r * 129 + c4 + 2] = x.z;
        sk[r * 129 + c4 + 3] = x.w;
    }
    __syncthreads();

    // K^T with seq-perm, coalesced writes over p
    float* kt = g_ktp + (size_t)bh * Dd * Ss + base;
    for (int i = tid; i < Dd * 64; i += 256) {
        int c = i >> 6, p = i & 63;
        int pr = ((p & 7) << 3) | (p >> 3);   // perm (involution)
        kt[(size_t)c * Ss + p] = __uint_as_float(f2tf(sk[pr * 129 + c]));
    }

    // V gathered, row-major with col-perm (writes stay within each 512B row)
    float* vt = g_vtp + ((size_t)bh * Ss + base) * Dd;
    for (int i = tid; i < 64 * 32; i += 256) {
        int r = i >> 5, c4 = (i & 31) << 2;
        float4 x = *(const float4*)(vg + (size_t)sidx[r] * Dd + c4);
        float a[4] = {x.x, x.y, x.z, x.w};
#pragma unroll
        for (int u = 0; u < 4; u++) {
            int c = c4 + u;
            vt[(size_t)r * Dd + ((c & 7) << 4) + (c >> 3)] = __uint_as_float(f2tf(a[u]));
        }
    }
}

// ---------------- main kernel ----------------
// smem words: sK[2][128*66]=16896 | sV[2][64*132]=16896 | sel 2048  => 35840 w = 140KB
__global__ void __launch_bounds__(NT, 1)
fa_kernel(const float* __restrict__ q, float* __restrict__ out) {
    extern __shared__ uint32_t sm[];
    uint32_t* sKb[2] = {sm, sm + 8448};
    uint32_t* sVb[2] = {sm + 16896, sm + 25344};
    float* sMask = (float*)(sm + 33792);

    const int tid = threadIdx.x, warp = tid >> 5, lane = tid & 31;
    const int g = lane >> 2, tig = lane & 3;
    const int qb = blockIdx.x, bh = blockIdx.y, b = bh >> 4;  // Hh=16
    const size_t bh_base = (size_t)bh * Ss * Dd;

    const int npad = g_cnt[b];
    const int ntiles = npad >> 6;
    for (int i = tid; i < npad; i += NT)
        sMask[i] = g_sel[b][i];

    // stage Q through the K smem region, build pre-scaled tf32 A-fragments
    float* sQ = (float*)sm;
    const float* qg = q + bh_base + (size_t)qb * BM * Dd;
    for (int i = tid; i < BM * 32; i += NT) {
        int r = i >> 5, c = (i & 31) << 2;
        *(float4*)(sQ + r * 132 + c) = *(const float4*)(qg + (size_t)r * Dd + c);
    }
    __syncthreads();
    const int r0 = warp * 16 + g, r1 = r0 + 8;
    uint32_t qf[16][4];
#pragma unroll
    for (int kk = 0; kk < 16; kk++) {
        qf[kk][0] = f2tf(sQ[r0 * 132 + kk * 8 + tig] * SCALE_F);
        qf[kk][1] = f2tf(sQ[r1 * 132 + kk * 8 + tig] * SCALE_F);
        qf[kk][2] = f2tf(sQ[r0 * 132 + kk * 8 + tig + 4] * SCALE_F);
        qf[kk][3] = f2tf(sQ[r1 * 132 + kk * 8 + tig + 4] * SCALE_F);
    }
    __syncthreads();

    const uint32_t sbase = (uint32_t)__cvta_generic_to_shared(sm);
    const uint32_t kaddr[2] = {sbase, sbase + 8448u * 4u};
    const uint32_t vaddr[2] = {sbase + 16896u * 4u, sbase + 25344u * 4u};
    const float* ktsrc = g_ktp + (size_t)bh * Dd * Ss;
    const float* vtsrc = g_vtp + (size_t)bh * Ss * Dd;

    auto issue_tile = [&](int t, int bi) {
        const float* ks = ktsrc + (size_t)t * 64;
        const float* vs = vtsrc + (size_t)t * 64 * Dd;
        uint32_t kb = kaddr[bi], vb = vaddr[bi];
#pragma unroll
        for (int i = 0; i < 16; i++) {          // K: 4096 8B-chunks
            int ch = tid + i * NT;
            int c = ch >> 5, po = (ch & 31) << 1;
            cp8(kb + (uint32_t)(c * KST + po) * 4u, ks + (size_t)c * Ss + po);
        }
#pragma unroll
        for (int i = 0; i < 8; i++) {           // V: 2048 16B-chunks
            int ch = tid + i * NT;
            int r = ch >> 5, po = (ch & 31) << 2;
            cp16(vb + (uint32_t)(r * VST + po) * 4u, vs + (size_t)r * Dd + po);
        }
        asm volatile("cp.async.commit_group;" ::: "memory");
    };

    float oa[16][4];
#pragma unroll
    for (int n = 0; n < 16; n++)
        oa[n][0] = oa[n][1] = oa[n][2] = oa[n][3] = 0.f;
    float l0 = 0.f, l1 = 0.f;

    issue_tile(0, 0);

#pragma unroll 1
    for (int t = 0; t < ntiles; t++) {
        const int bi = t & 1;
        if (t + 1 < ntiles) {
            issue_tile(t + 1, bi ^ 1);
            asm volatile("cp.async.wait_group 1;" ::: "memory");
        } else {
            asm volatile("cp.async.wait_group 0;" ::: "memory");
        }
        __syncthreads();
        const uint32_t* Kb = sKb[bi];
        const uint32_t* Vb = sVb[bi];

        // ---- S = (Q*scale) K^T : conflict-free LDS.64 fragments ----
        float sa[8][4];
#pragma unroll
        for (int j = 0; j < 8; j++)
            sa[j][0] = sa[j][1] = sa[j][2] = sa[j][3] = 0.f;
#pragma unroll
        for (int kk = 0; kk < 16; kk++) {
            const uint32_t* kr0 = Kb + (kk * 8 + tig) * KST + g * 8;
            const uint32_t* kr1 = kr0 + 4 * KST;
            uint2 u0 = *(const uint2*)(kr0 + 0), u1 = *(const uint2*)(kr0 + 2);
            uint2 u2 = *(const uint2*)(kr0 + 4), u3 = *(const uint2*)(kr0 + 6);
            uint2 w0 = *(const uint2*)(kr1 + 0), w1 = *(const uint2*)(kr1 + 2);
            uint2 w2 = *(const uint2*)(kr1 + 4), w3 = *(const uint2*)(kr1 + 6);
            mma8(sa[0], qf[kk][0], qf[kk][1], qf[kk][2], qf[kk][3], u0.x, w0.x);
            mma8(sa[1], qf[kk][0], qf[kk][1], qf[kk][2], qf[kk][3], u0.y, w0.y);
            mma8(sa[2], qf[kk][0], qf[kk][1], qf[kk][2], qf[kk][3], u1.x, w1.x);
            mma8(sa[3], qf[kk][0], qf[kk][1], qf[kk][2], qf[kk][3], u1.y, w1.y);
            mma8(sa[4], qf[kk][0], qf[kk][1], qf[kk][2], qf[kk][3], u2.x, w2.x);
            mma8(sa[5], qf[kk][0], qf[kk][1], qf[kk][2], qf[kk][3], u2.y, w2.y);
            mma8(sa[6], qf[kk][0], qf[kk][1], qf[kk][2], qf[kk][3], u3.x, w3.x);
            mma8(sa[7], qf[kk][0], qf[kk][1], qf[kk][2], qf[kk][3], u3.y, w3.y);
        }

        // ---- p = exp(s) * sel  (shift-invariant softmax; padding sel=0) ----
        const int n0 = t * 64;
#pragma unroll
        for (int j = 0; j < 8; j++) {
            float2 ms = *(const float2*)(sMask + n0 + j * 8 + 2 * tig);
            float p00 = __expf(sa[j][0]) * ms.x;
            float p01 = __expf(sa[j][1]) * ms.y;
            float p10 = __expf(sa[j][2]) * ms.x;
            float p11 = __expf(sa[j][3]) * ms.y;
            l0 += p00 + p01;
            l1 += p10 + p11;
            sa[j][0] = __uint_as_float(f2tf(p00));
            sa[j][1] = __uint_as_float(f2tf(p01));
            sa[j][2] = __uint_as_float(f2tf(p10));
            sa[j][3] = __uint_as_float(f2tf(p11));
        }

        // ---- O += P V : shfl layout conversion + conflict-free LDS.128 V frags ----
#pragma unroll
        for (int kk = 0; kk < 8; kk++) {
            uint32_t c0 = __float_as_uint(sa[kk][0]);
            uint32_t c1 = __float_as_uint(sa[kk][1]);
            uint32_t c2 = __float_as_uint(sa[kk][2]);
            uint32_t c3 = __float_as_uint(sa[kk][3]);
            int src0 = (lane & 28) | (tig >> 1);
            int src1 = src0 + 2;
            uint32_t x0 = __shfl_sync(0xffffffffu, c0, src0);
            uint32_t x1 = __shfl_sync(0xffffffffu, c1, src0);
            uint32_t y0 = __shfl_sync(0xffffffffu, c0, src1);
            uint32_t y1 = __shfl_sync(0xffffffffu, c1, src1);
            uint32_t a0 = (tig & 1) ? x1 : x0;
            uint32_t a2 = (tig & 1) ? y1 : y0;
            x0 = __shfl_sync(0xffffffffu, c2, src0);
            x1 = __shfl_sync(0xffffffffu, c3, src0);
            y0 = __shfl_sync(0xffffffffu, c2, src1);
            y1 = __shfl_sync(0xffffffffu, c3, src1);
            uint32_t a1 = (tig & 1) ? x1 : x0;
            uint32_t a3 = (tig & 1) ? y1 : y0;

            const uint32_t* vr0 = Vb + (kk * 8 + tig) * VST + g * 16;
            const uint32_t* vr1 = vr0 + 4 * VST;
            uint4 v0 = *(const uint4*)(vr0 + 0), v1 = *(const uint4*)(vr0 + 4);
            uint4 v2 = *(const uint4*)(vr0 + 8), v3 = *(const uint4*)(vr0 + 12);
            uint4 z0 = *(const uint4*)(vr1 + 0), z1 = *(const uint4*)(vr1 + 4);
            uint4 z2 = *(const uint4*)(vr1 + 8), z3 = *(const uint4*)(vr1 + 12);
            mma8(oa[0],  a0, a1, a2, a3, v0.x, z0.x);
            mma8(oa[1],  a0, a1, a2, a3, v0.y, z0.y);
            mma8(oa[2],  a0, a1, a2, a3, v0.z, z0.z);
            mma8(oa[3],  a0, a1, a2, a3, v0.w, z0.w);
            mma8(oa[4],  a0, a1, a2, a3, v1.x, z1.x);
            mma8(oa[5],  a0, a1, a2, a3, v1.y, z1.y);
            mma8(oa[6],  a0, a1, a2, a3, v1.z, z1.z);
            mma8(oa[7],  a0, a1, a2, a3, v1.w, z1.w);
            mma8(oa[8],  a0, a1, a2, a3, v2.x, z2.x);
            mma8(oa[9],  a0, a1, a2, a3, v2.y, z2.y);
            mma8(oa[10], a0, a1, a2, a3, v2.z, z2.z);
            mma8(oa[11], a0, a1, a2, a3, v2.w, z2.w);
            mma8(oa[12], a0, a1, a2, a3, v3.x, z3.x);
            mma8(oa[13], a0, a1, a2, a3, v3.y, z3.y);
            mma8(oa[14], a0, a1, a2, a3, v3.z, z3.z);
            mma8(oa[15], a0, a1, a2, a3, v3.w, z3.w);
        }
        __syncthreads();  // compute done before buffer bi gets re-issued
    }

    // ---- epilogue: reduce l over the 4-thread group, normalize, store ----
    l0 += __shfl_xor_sync(0xffffffffu, l0, 1);
    l0 += __shfl_xor_sync(0xffffffffu, l0, 2);
    l1 += __shfl_xor_sync(0xffffffffu, l1, 1);
    l1 += __shfl_xor_sync(0xffffffffu, l1, 2);
    float i0 = 1.f / l0, i1 = 1.f / l1;
    float* og = out + bh_base + (size_t)qb * BM * Dd;
#pragma unroll
    for (int n = 0; n < 16; n++) {
        int c = n * 8 + 2 * tig;
        *(float2*)(og + (size_t)r0 * Dd + c) = make_float2(oa[n][0] * i0, oa[n][1] * i0);
        *(float2*)(og + (size_t)r1 * Dd + c) = make_float2(oa[n][2] * i1, oa[n][3] * i1);
    }
}

extern "C" void kernel_launch(void* const* d_in, const int* in_sizes, int n_in,
                              void* d_out, int out_size) {
    (void)in_sizes; (void)n_in; (void)out_size;
    const float* q = (const float*)d_in[0];
    const float* k = (const float*)d_in[1];
    const float* v = (const float*)d_in[2];
    const int* mask = (const int*)d_in[3];
    float* out = (float*)d_out;

    compact_kernel<<<Bc, 256>>>(mask);
    prep_kernel<<<dim3(Ss / 64, Bc * Hh), 256>>>(k, v);

    constexpr int SMEM_BYTES = 35840 * 4;  // 143,360
    cudaFuncSetAttribute(fa_kernel, cudaFuncAttributeMaxDynamicSharedMemorySize,
                         SMEM_BYTES);
    fa_kernel<<<dim3(Ss / BM, Bc * Hh), NT, SMEM_BYTES>>>(q, out);
}

// round 6
// speedup vs baseline: 2.1552x; 1.0700x over previous
#include <cuda_runtime.h>
#include <cstdint>

// Problem: B=2, H=16, S=2048, D=128, fp32 in/out, int32 mask over keys.
// Masked keys (~50%) contribute exactly zero -> K/V compacted once (prep).
// Main kernel: BM=64 q-rows, 128 threads, 2 CTAs/SM (independent barriers ->
// cross-CTA latency hiding). K double-buffered, V single-buffered.
constexpr int Bc = 2, Hh = 16, Ss = 2048, Dd = 128;
constexpr int BM = 64;          // queries per block (4 warps x 16 rows)
constexpr int NT = 128;         // threads
constexpr int KST = 66;         // K^T smem row stride (words) -> LDS.64 conflict-free
constexpr int VST = 132;        // V smem row stride (words)  -> LDS.128 conflict-free
constexpr float SCALE_F = 0.08838834764831845f;  // 1/sqrt(128)

// Compaction tables
__device__ int g_cnt[Bc];
__device__ int g_idx[Bc][Ss];
__device__ float g_sel[Bc][Ss];
// Pre-converted tf32 K (transposed + seq-permuted) and V (col-permuted), compacted.
__device__ __align__(16) float g_ktp[(size_t)Bc * Hh * Dd * Ss];
__device__ __align__(16) float g_vtp[(size_t)Bc * Hh * Ss * Dd];

__device__ __forceinline__ uint32_t f2tf(float x) {
    uint32_t r;
    asm("cvt.rna.tf32.f32 %0, %1;" : "=r"(r) : "f"(x));
    return r;
}

__device__ __forceinline__ void mma8(float* d, uint32_t a0, uint32_t a1, uint32_t a2,
                                     uint32_t a3, uint32_t b0, uint32_t b1) {
    asm volatile(
        "mma.sync.aligned.m16n8k8.row.col.f32.tf32.tf32.f32 "
        "{%0,%1,%2,%3},{%4,%5,%6,%7},{%8,%9},{%0,%1,%2,%3};"
        : "+f"(d[0]), "+f"(d[1]), "+f"(d[2]), "+f"(d[3])
        : "r"(a0), "r"(a1), "r"(a2), "r"(a3), "r"(b0), "r"(b1));
}

__device__ __forceinline__ void cp16(uint32_t dst, const void* src) {
    asm volatile("cp.async.ca.shared.global [%0], [%1], 16;" :: "r"(dst), "l"(src));
}
__device__ __forceinline__ void cp8(uint32_t dst, const void* src) {
    asm volatile("cp.async.ca.shared.global [%0], [%1], 8;" :: "r"(dst), "l"(src));
}
#define CP_COMMIT() asm volatile("cp.async.commit_group;" ::: "memory")

// ---------------- pass 1: compact unmasked key indices ----------------
__global__ void __launch_bounds__(256) compact_kernel(const int* __restrict__ mask) {
    __shared__ int wcnt[64], woff[64];
    __shared__ int s_tot[2];
    const int b = blockIdx.x, tid = threadIdx.x;
    const int warp = tid >> 5, lane = tid & 31;

    for (int ch = warp; ch < 64; ch += 8) {
        int m = mask[b * Ss + ch * 32 + lane] != 0;
        unsigned bal = __ballot_sync(0xffffffffu, m);
        if (lane == 0) wcnt[ch] = __popc(bal);
    }
    __syncthreads();
    if (tid == 0) {
        int s = 0;
        for (int i = 0; i < 64; i++) { woff[i] = s; s += wcnt[i]; }
        int pad = (s + 63) & ~63;
        g_cnt[b] = pad;
        s_tot[0] = s;
        s_tot[1] = pad;
    }
    __syncthreads();
    const int total = s_tot[0], pad = s_tot[1];
    for (int ch = warp; ch < 64; ch += 8) {
        int src = ch * 32 + lane;
        int m = mask[b * Ss + src] != 0;
        unsigned bal = __ballot_sync(0xffffffffu, m);
        if (m) {
            int pos = woff[ch] + __popc(bal & ((1u << lane) - 1u));
            g_idx[b][pos] = src;
            g_sel[b][pos] = 1.0f;
        }
    }
    __syncthreads();
    for (int i = total + tid; i < pad; i += 256) {
        g_idx[b][i] = 0;
        g_sel[b][i] = 0.0f;
    }
}

// ---------------- pass 2: gather + tf32 convert + layout transform ----------------
__global__ void __launch_bounds__(256) prep_kernel(const float* __restrict__ k,
                                                   const float* __restrict__ v) {
    __shared__ float sk[64 * 129];
    __shared__ int sidx[64];
    const int t = blockIdx.x, bh = blockIdx.y, tid = threadIdx.x;
    const int b = bh >> 4;
    if (t * 64 >= g_cnt[b]) return;
    const int base = t * 64;
    const float* kg = k + (size_t)bh * Ss * Dd;
    const float* vg = v + (size_t)bh * Ss * Dd;

    if (tid < 64) sidx[tid] = g_idx[b][base + tid];
    __syncthreads();

    for (int i = tid; i < 64 * 32; i += 256) {
        int r = i >> 5, c4 = (i & 31) << 2;
        float4 x = *(const float4*)(kg + (size_t)sidx[r] * Dd + c4);
        sk[r * 129 + c4 + 0] = x.x;
        sk[r * 129 + c4 + 1] = x.y;
        sk[r * 129 + c4 + 2] = x.z;
        sk[r * 129 + c4 + 3] = x.w;
    }
    __syncthreads();

    float* kt = g_ktp + (size_t)bh * Dd * Ss + base;
    for (int i = tid; i < Dd * 64; i += 256) {
        int c = i >> 6, p = i & 63;
        int pr = ((p & 7) << 3) | (p >> 3);
        kt[(size_t)c * Ss + p] = __uint_as_float(f2tf(sk[pr * 129 + c]));
    }

    float* vt = g_vtp + ((size_t)bh * Ss + base) * Dd;
    for (int i = tid; i < 64 * 32; i += 256) {
        int r = i >> 5, c4 = (i & 31) << 2;
        float4 x = *(const float4*)(vg + (size_t)sidx[r] * Dd + c4);
        float a[4] = {x.x, x.y, x.z, x.w};
#pragma unroll
        for (int u = 0; u < 4; u++) {
            int c = c4 + u;
            vt[(size_t)r * Dd + ((c & 7) << 4) + (c >> 3)] = __uint_as_float(f2tf(a[u]));
        }
    }
}

// ---------------- main kernel ----------------
// dyn smem words: K0 8448 | K1 8448 | V 8448 | mask 2048 => 27392 w = 107KB -> 2 CTA/SM
__global__ void __launch_bounds__(NT, 2)
fa_kernel(const float* __restrict__ q, float* __restrict__ out) {
    extern __shared__ uint32_t sm[];
    uint32_t* sKb[2] = {sm, sm + 8448};
    uint32_t* sV = sm + 16896;
    float* sMask = (float*)(sm + 25344);

    const int tid = threadIdx.x, warp = tid >> 5, lane = tid & 31;
    const int g = lane >> 2, tig = lane & 3;
    const int qb = blockIdx.x, bh = blockIdx.y, b = bh >> 4;  // Hh=16
    const size_t bh_base = (size_t)bh * Ss * Dd;

    const int npad = g_cnt[b];
    const int ntiles = npad >> 6;

    const uint32_t sbase = (uint32_t)__cvta_generic_to_shared(sm);
    const uint32_t kaddr[2] = {sbase, sbase + 8448u * 4u};
    const uint32_t vaddr = sbase + 16896u * 4u;
    const float* ktsrc = g_ktp + (size_t)bh * Dd * Ss;
    const float* vtsrc = g_vtp + (size_t)bh * Ss * Dd;

    auto issue_k = [&](int t, int par) {
        const float* ks = ktsrc + (size_t)t * 64;
        uint32_t kb = kaddr[par];
#pragma unroll
        for (int i = 0; i < 32; i++) {          // 4096 8B-chunks / 128 threads
            int ch = tid + i * NT;
            int c = ch >> 5, po = (ch & 31) << 1;
            cp8(kb + (uint32_t)(c * KST + po) * 4u, ks + (size_t)c * Ss + po);
        }
        CP_COMMIT();
    };
    auto issue_v = [&](int t) {
        const float* vs = vtsrc + (size_t)t * 64 * Dd;
#pragma unroll
        for (int i = 0; i < 16; i++) {          // 2048 16B-chunks / 128 threads
            int ch = tid + i * NT;
            int r = ch >> 5, po = (ch & 31) << 2;
            cp16(vaddr + (uint32_t)(r * VST + po) * 4u, vs + (size_t)r * Dd + po);
        }
        CP_COMMIT();
    };

    // prologue: K(0) in flight first, then stage Q (through V region) + mask
    issue_k(0, 0);
    for (int i = tid; i < npad; i += NT)
        sMask[i] = g_sel[b][i];
    float* sQ = (float*)sV;
    const float* qg = q + bh_base + (size_t)qb * BM * Dd;
    for (int i = tid; i < BM * 32; i += NT) {
        int r = i >> 5, c = (i & 31) << 2;
        *(float4*)(sQ + r * 132 + c) = *(const float4*)(qg + (size_t)r * Dd + c);
    }
    __syncthreads();
    const int r0 = warp * 16 + g, r1 = r0 + 8;
    uint32_t qf[16][4];
#pragma unroll
    for (int kk = 0; kk < 16; kk++) {
        qf[kk][0] = f2tf(sQ[r0 * 132 + kk * 8 + tig] * SCALE_F);
        qf[kk][1] = f2tf(sQ[r1 * 132 + kk * 8 + tig] * SCALE_F);
        qf[kk][2] = f2tf(sQ[r0 * 132 + kk * 8 + tig + 4] * SCALE_F);
        qf[kk][3] = f2tf(sQ[r1 * 132 + kk * 8 + tig + 4] * SCALE_F);
    }

    float oa[16][4];
#pragma unroll
    for (int n = 0; n < 16; n++)
        oa[n][0] = oa[n][1] = oa[n][2] = oa[n][3] = 0.f;
    float l0 = 0.f, l1 = 0.f;

#pragma unroll 1
    for (int t = 0; t < ntiles; t++) {
        const int par = t & 1;
        // K(t) is the only possibly-pending group here
        asm volatile("cp.async.wait_group 0;" ::: "memory");
        __syncthreads();           // K(t) visible; V buffer free (PV(t-1) done)
        issue_v(t);                // hidden under S-MMA + exp

        // ---- S = (Q*scale) K^T ----
        const uint32_t* Kb = sKb[par];
        float sa[8][4];
#pragma unroll
        for (int j = 0; j < 8; j++)
            sa[j][0] = sa[j][1] = sa[j][2] = sa[j][3] = 0.f;
#pragma unroll
        for (int kk = 0; kk < 16; kk++) {
            const uint32_t* kr0 = Kb + (kk * 8 + tig) * KST + g * 8;
            const uint32_t* kr1 = kr0 + 4 * KST;
            uint2 u0 = *(const uint2*)(kr0 + 0), u1 = *(const uint2*)(kr0 + 2);
            uint2 u2 = *(const uint2*)(kr0 + 4), u3 = *(const uint2*)(kr0 + 6);
            uint2 w0 = *(const uint2*)(kr1 + 0), w1 = *(const uint2*)(kr1 + 2);
            uint2 w2 = *(const uint2*)(kr1 + 4), w3 = *(const uint2*)(kr1 + 6);
            mma8(sa[0], qf[kk][0], qf[kk][1], qf[kk][2], qf[kk][3], u0.x, w0.x);
            mma8(sa[1], qf[kk][0], qf[kk][1], qf[kk][2], qf[kk][3], u0.y, w0.y);
            mma8(sa[2], qf[kk][0], qf[kk][1], qf[kk][2], qf[kk][3], u1.x, w1.x);
            mma8(sa[3], qf[kk][0], qf[kk][1], qf[kk][2], qf[kk][3], u1.y, w1.y);
            mma8(sa[4], qf[kk][0], qf[kk][1], qf[kk][2], qf[kk][3], u2.x, w2.x);
            mma8(sa[5], qf[kk][0], qf[kk][1], qf[kk][2], qf[kk][3], u2.y, w2.y);
            mma8(sa[6], qf[kk][0], qf[kk][1], qf[kk][2], qf[kk][3], u3.x, w3.x);
            mma8(sa[7], qf[kk][0], qf[kk][1], qf[kk][2], qf[kk][3], u3.y, w3.y);
        }

        // K(t+1) into the buffer K(t-1) used; hidden under exp + PV
        if (t + 1 < ntiles) issue_k(t + 1, par ^ 1);

        // ---- p = exp(s) * sel ----
        const int n0 = t * 64;
#pragma unroll
        for (int j = 0; j < 8; j++) {
            float2 ms = *(const float2*)(sMask + n0 + j * 8 + 2 * tig);
            float p00 = __expf(sa[j][0]) * ms.x;
            float p01 = __expf(sa[j][1]) * ms.y;
            float p10 = __expf(sa[j][2]) * ms.x;
            float p11 = __expf(sa[j][3]) * ms.y;
            l0 += p00 + p01;
            l1 += p10 + p11;
            sa[j][0] = __uint_as_float(f2tf(p00));
            sa[j][1] = __uint_as_float(f2tf(p01));
            sa[j][2] = __uint_as_float(f2tf(p10));
            sa[j][3] = __uint_as_float(f2tf(p11));
        }

        // wait V(t) (leave K(t+1) pending if it exists)
        if (t + 1 < ntiles)
            asm volatile("cp.async.wait_group 1;" ::: "memory");
        else
            asm volatile("cp.async.wait_group 0;" ::: "memory");
        __syncthreads();           // V visible to all warps

        // ---- O += P V ----
#pragma unroll
        for (int kk = 0; kk < 8; kk++) {
            uint32_t c0 = __float_as_uint(sa[kk][0]);
            uint32_t c1 = __float_as_uint(sa[kk][1]);
            uint32_t c2 = __float_as_uint(sa[kk][2]);
            uint32_t c3 = __float_as_uint(sa[kk][3]);
            int src0 = (lane & 28) | (tig >> 1);
            int src1 = src0 + 2;
            uint32_t x0 = __shfl_sync(0xffffffffu, c0, src0);
            uint32_t x1 = __shfl_sync(0xffffffffu, c1, src0);
            uint32_t y0 = __shfl_sync(0xffffffffu, c0, src1);
            uint32_t y1 = __shfl_sync(0xffffffffu, c1, src1);
            uint32_t a0 = (tig & 1) ? x1 : x0;
            uint32_t a2 = (tig & 1) ? y1 : y0;
            x0 = __shfl_sync(0xffffffffu, c2, src0);
            x1 = __shfl_sync(0xffffffffu, c3, src0);
            y0 = __shfl_sync(0xffffffffu, c2, src1);
            y1 = __shfl_sync(0xffffffffu, c3, src1);
            uint32_t a1 = (tig & 1) ? x1 : x0;
            uint32_t a3 = (tig & 1) ? y1 : y0;

            const uint32_t* vr0 = sV + (kk * 8 + tig) * VST + g * 16;
            const uint32_t* vr1 = vr0 + 4 * VST;
            uint4 v0 = *(const uint4*)(vr0 + 0), v1 = *(const uint4*)(vr0 + 4);
            uint4 v2 = *(const uint4*)(vr0 + 8), v3 = *(const uint4*)(vr0 + 12);
            uint4 z0 = *(const uint4*)(vr1 + 0), z1 = *(const uint4*)(vr1 + 4);
            uint4 z2 = *(const uint4*)(vr1 + 8), z3 = *(const uint4*)(vr1 + 12);
            mma8(oa[0],  a0, a1, a2, a3, v0.x, z0.x);
            mma8(oa[1],  a0, a1, a2, a3, v0.y, z0.y);
            mma8(oa[2],  a0, a1, a2, a3, v0.z, z0.z);
            mma8(oa[3],  a0, a1, a2, a3, v0.w, z0.w);
            mma8(oa[4],  a0, a1, a2, a3, v1.x, z1.x);
            mma8(oa[5],  a0, a1, a2, a3, v1.y, z1.y);
            mma8(oa[6],  a0, a1, a2, a3, v1.z, z1.z);
            mma8(oa[7],  a0, a1, a2, a3, v1.w, z1.w);
            mma8(oa[8],  a0, a1, a2, a3, v2.x, z2.x);
            mma8(oa[9],  a0, a1, a2, a3, v2.y, z2.y);
            mma8(oa[10], a0, a1, a2, a3, v2.z, z2.z);
            mma8(oa[11], a0, a1, a2, a3, v2.w, z2.w);
            mma8(oa[12], a0, a1, a2, a3, v3.x, z3.x);
            mma8(oa[13], a0, a1, a2, a3, v3.y, z3.y);
            mma8(oa[14], a0, a1, a2, a3, v3.z, z3.z);
            mma8(oa[15], a0, a1, a2, a3, v3.w, z3.w);
        }
    }

    // ---- epilogue ----
    l0 += __shfl_xor_sync(0xffffffffu, l0, 1);
    l0 += __shfl_xor_sync(0xffffffffu, l0, 2);
    l1 += __shfl_xor_sync(0xffffffffu, l1, 1);
    l1 += __shfl_xor_sync(0xffffffffu, l1, 2);
    float i0 = 1.f / l0, i1 = 1.f / l1;
    float* og = out + bh_base + (size_t)qb * BM * Dd;
#pragma unroll
    for (int n = 0; n < 16; n++) {
        int c = n * 8 + 2 * tig;
        *(float2*)(og + (size_t)r0 * Dd + c) = make_float2(oa[n][0] * i0, oa[n][1] * i0);
        *(float2*)(og + (size_t)r1 * Dd + c) = make_float2(oa[n][2] * i1, oa[n][3] * i1);
    }
}

extern "C" void kernel_launch(void* const* d_in, const int* in_sizes, int n_in,
                              void* d_out, int out_size) {
    (void)in_sizes; (void)n_in; (void)out_size;
    const float* q = (const float*)d_in[0];
    const float* k = (const float*)d_in[1];
    const float* v = (const float*)d_in[2];
    const int* mask = (const int*)d_in[3];
    float* out = (float*)d_out;

    compact_kernel<<<Bc, 256>>>(mask);
    prep_kernel<<<dim3(Ss / 64, Bc * Hh), 256>>>(k, v);

    constexpr int SMEM_BYTES = 27392 * 4;  // 109,568 -> 2 CTAs/SM
    cudaFuncSetAttribute(fa_kernel, cudaFuncAttributeMaxDynamicSharedMemorySize,
                         SMEM_BYTES);
    fa_kernel<<<dim3(Ss / BM, Bc * Hh), NT, SMEM_BYTES>>>(q, out);
}

// round 7
// speedup vs baseline: 4.0753x; 1.8909x over previous
#include <cuda_runtime.h>
#include <cuda_fp16.h>
#include <cstdint>

// Problem: B=2, H=16, S=2048, D=128, fp32 in/out, int32 mask over keys.
// Masked keys (~50%) contribute exactly zero -> K/V compacted once (prep).
// fp16 datapath (same 11-bit mantissa as tf32), m16n8k16 MMA, ldmatrix B-frags,
// P accumulator->A-fragment conversion is pure register packing (no shfl).
constexpr int Bc = 2, Hh = 16, Ss = 2048, Dd = 128;
constexpr int BM = 64;          // queries per block (4 warps x 16 rows)
constexpr int NT = 128;         // threads
constexpr float SCALE_F = 0.08838834764831845f;  // 1/sqrt(128)

// K tile row = 128 fp16 = 256B + 16B pad = 272B ; VT tile row = 64 fp16 = 128B + 16B = 144B
constexpr int KROWB = 272;
constexpr int VROWB = 144;
constexpr int KTILEB = 64 * KROWB;    // 17408
constexpr int VTILEB = 128 * VROWB;   // 18432

// Compaction tables
__device__ int g_cnt[Bc];
__device__ int g_idx[Bc][Ss];
__device__ float g_sel[Bc][Ss];
// fp16 operands, compacted: g_kh [bh][j][d] (no transpose), g_vth [bh][d][j]
__device__ __align__(16) __half g_kh[(size_t)Bc * Hh * Ss * Dd];
__device__ __align__(16) __half g_vth[(size_t)Bc * Hh * Dd * Ss];

__device__ __forceinline__ uint32_t f2h2(float lo, float hi) {
    __half2 h = __floats2half2_rn(lo, hi);
    return *(uint32_t*)&h;
}

__device__ __forceinline__ void mma16(float* d, uint32_t a0, uint32_t a1, uint32_t a2,
                                      uint32_t a3, uint32_t b0, uint32_t b1) {
    asm volatile(
        "mma.sync.aligned.m16n8k16.row.col.f32.f16.f16.f32 "
        "{%0,%1,%2,%3},{%4,%5,%6,%7},{%8,%9},{%0,%1,%2,%3};"
        : "+f"(d[0]), "+f"(d[1]), "+f"(d[2]), "+f"(d[3])
        : "r"(a0), "r"(a1), "r"(a2), "r"(a3), "r"(b0), "r"(b1));
}

__device__ __forceinline__ void ldsm4(uint32_t& t0, uint32_t& t1, uint32_t& t2,
                                      uint32_t& t3, uint32_t addr) {
    asm volatile("ldmatrix.sync.aligned.m8n8.x4.shared.b16 {%0,%1,%2,%3}, [%4];"
                 : "=r"(t0), "=r"(t1), "=r"(t2), "=r"(t3) : "r"(addr));
}

__device__ __forceinline__ void cp16(uint32_t dst, const void* src) {
    asm volatile("cp.async.ca.shared.global [%0], [%1], 16;" :: "r"(dst), "l"(src));
}
#define CP_COMMIT() asm volatile("cp.async.commit_group;" ::: "memory")

// ---------------- pass 1: compact unmasked key indices ----------------
__global__ void __launch_bounds__(256) compact_kernel(const int* __restrict__ mask) {
    __shared__ int wcnt[64], woff[64];
    __shared__ int s_tot[2];
    const int b = blockIdx.x, tid = threadIdx.x;
    const int warp = tid >> 5, lane = tid & 31;

    for (int ch = warp; ch < 64; ch += 8) {
        int m = mask[b * Ss + ch * 32 + lane] != 0;
        unsigned bal = __ballot_sync(0xffffffffu, m);
        if (lane == 0) wcnt[ch] = __popc(bal);
    }
    __syncthreads();
    if (tid == 0) {
        int s = 0;
        for (int i = 0; i < 64; i++) { woff[i] = s; s += wcnt[i]; }
        int pad = (s + 63) & ~63;
        g_cnt[b] = pad;
        s_tot[0] = s;
        s_tot[1] = pad;
    }
    __syncthreads();
    const int total = s_tot[0], pad = s_tot[1];
    for (int ch = warp; ch < 64; ch += 8) {
        int src = ch * 32 + lane;
        int m = mask[b * Ss + src] != 0;
        unsigned bal = __ballot_sync(0xffffffffu, m);
        if (m) {
            int pos = woff[ch] + __popc(bal & ((1u << lane) - 1u));
            g_idx[b][pos] = src;
            g_sel[b][pos] = 1.0f;
        }
    }
    __syncthreads();
    for (int i = total + tid; i < pad; i += 256) {
        g_idx[b][i] = 0;
        g_sel[b][i] = 0.0f;
    }
}

// ---------------- pass 2: gather + fp16 convert (+ V transpose) ----------------
__global__ void __launch_bounds__(256) prep_kernel(const float* __restrict__ k,
                                                   const float* __restrict__ v) {
    __shared__ float sv[64 * 129];
    __shared__ int sidx[64];
    const int t = blockIdx.x, bh = blockIdx.y, tid = threadIdx.x;
    const int b = bh >> 4;
    if (t * 64 >= g_cnt[b]) return;
    const int base = t * 64;
    const float* kg = k + (size_t)bh * Ss * Dd;
    const float* vg = v + (size_t)bh * Ss * Dd;

    if (tid < 64) sidx[tid] = g_idx[b][base + tid];
    __syncthreads();

    // K: gather rows, convert to fp16, no transpose (coalesced both ways)
    uint32_t* ko = (uint32_t*)(g_kh + ((size_t)bh * Ss + base) * Dd);
    for (int i = tid; i < 64 * 32; i += 256) {
        int r = i >> 5, c4 = (i & 31) << 2;
        float4 x = *(const float4*)(kg + (size_t)sidx[r] * Dd + c4);
        ko[(r * Dd + c4) >> 1] = f2h2(x.x, x.y);
        ko[((r * Dd + c4) >> 1) + 1] = f2h2(x.z, x.w);
    }

    // V: gather rows into smem fp32, then write transposed fp16 [d][key]
    for (int i = tid; i < 64 * 32; i += 256) {
        int r = i >> 5, c4 = (i & 31) << 2;
        float4 x = *(const float4*)(vg + (size_t)sidx[r] * Dd + c4);
        sv[r * 129 + c4 + 0] = x.x; sv[r * 129 + c4 + 1] = x.y;
        sv[r * 129 + c4 + 2] = x.z; sv[r * 129 + c4 + 3] = x.w;
    }
    __syncthreads();
    uint32_t* vo = (uint32_t*)(g_vth + (size_t)bh * Dd * Ss);
    for (int i = tid; i < 128 * 32; i += 256) {
        int d = i >> 5, kp = i & 31;           // key pair 2kp, 2kp+1
        uint32_t h = f2h2(sv[(2 * kp) * 129 + d], sv[(2 * kp + 1) * 129 + d]);
        vo[((size_t)d * Ss + base) / 2 + kp] = h;
    }
}

// ---------------- main kernel ----------------
// dyn smem bytes: K0 17408 | K1 17408 | V0 18432 | V1 18432 | mask 8192 = 79872
__global__ void __launch_bounds__(NT, 2)
fa_kernel(const float* __restrict__ q, float* __restrict__ out) {
    extern __shared__ char sm[];
    const uint32_t sbase = (uint32_t)__cvta_generic_to_shared(sm);
    const uint32_t Kaddr[2] = {sbase, sbase + KTILEB};
    const uint32_t Vaddr[2] = {sbase + 2 * KTILEB, sbase + 2 * KTILEB + VTILEB};
    float* sMask = (float*)(sm + 2 * KTILEB + 2 * VTILEB);
    float* sQ = (float*)(sm + 2 * KTILEB);     // V0+V1 region (36KB >= 33.8KB), pre-loop only

    const int tid = threadIdx.x, warp = tid >> 5, lane = tid & 31;
    const int g = lane >> 2, tig = lane & 3;
    const int qb = blockIdx.x, bh = blockIdx.y, b = bh >> 4;  // Hh=16
    const size_t bh_base = (size_t)bh * Ss * Dd;

    const int npad = g_cnt[b];
    const int ntiles = npad >> 6;

    for (int i = tid; i < npad; i += NT)
        sMask[i] = g_sel[b][i];

    // stage Q fp32 in V region, build pre-scaled fp16 A-fragments, then free it
    const float* qg = q + bh_base + (size_t)qb * BM * Dd;
    for (int i = tid; i < BM * 32; i += NT) {
        int r = i >> 5, c = (i & 31) << 2;
        *(float4*)(sQ + r * 132 + c) = *(const float4*)(qg + (size_t)r * Dd + c);
    }
    __syncthreads();
    const int r0 = warp * 16 + g, r1 = r0 + 8;
    uint32_t qf[8][4];
#pragma unroll
    for (int kk = 0; kk < 8; kk++) {
        const float* q0 = sQ + r0 * 132 + kk * 16 + 2 * tig;
        const float* q1 = sQ + r1 * 132 + kk * 16 + 2 * tig;
        qf[kk][0] = f2h2(q0[0] * SCALE_F, q0[1] * SCALE_F);
        qf[kk][1] = f2h2(q1[0] * SCALE_F, q1[1] * SCALE_F);
        qf[kk][2] = f2h2(q0[8] * SCALE_F, q0[9] * SCALE_F);
        qf[kk][3] = f2h2(q1[8] * SCALE_F, q1[9] * SCALE_F);
    }
    __syncthreads();   // everyone done with sQ before V buffers get written

    const __half* ksrc = g_kh + (size_t)bh * Ss * Dd;
    const __half* vsrc = g_vth + (size_t)bh * Dd * Ss;

    auto issue_tile = [&](int t, int bi) {
        const __half* ks = ksrc + (size_t)t * 64 * Dd;
#pragma unroll
        for (int i = 0; i < 8; i++) {          // K: 64 rows x 16 chunks of 16B
            int ch = tid + i * NT;
            int r = ch >> 4, c = ch & 15;
            cp16(Kaddr[bi] + r * KROWB + c * 16, ks + r * Dd + c * 8);
        }
        const __half* vs = vsrc + (size_t)t * 64;
#pragma unroll
        for (int i = 0; i < 8; i++) {          // VT: 128 rows x 8 chunks of 16B
            int ch = tid + i * NT;
            int r = ch >> 3, c = ch & 7;
            cp16(Vaddr[bi] + r * VROWB + c * 16, vs + (size_t)r * Ss + c * 8);
        }
        CP_COMMIT();
    };

    // ldmatrix per-lane row addressing (x4: lanes 0-7 mat0, 8-15 mat1, ...)
    const int mi = lane >> 3, mrow = lane & 7;
    // K: matrices (jp-octet pair x k-halves): row = 8*(2jp + mi/2) + mrow, byte +16*(mi&1)
    const uint32_t krow_off = (8 * (mi >> 1) + mrow) * KROWB + 16 * (mi & 1);
    // VT: same pattern with VROWB
    const uint32_t vrow_off = (8 * (mi >> 1) + mrow) * VROWB + 16 * (mi & 1);

    float oa[16][4];
#pragma unroll
    for (int n = 0; n < 16; n++)
        oa[n][0] = oa[n][1] = oa[n][2] = oa[n][3] = 0.f;
    float l0 = 0.f, l1 = 0.f;

    issue_tile(0, 0);

#pragma unroll 1
    for (int t = 0; t < ntiles; t++) {
        const int bi = t & 1;
        if (t + 1 < ntiles) {
            issue_tile(t + 1, bi ^ 1);
            asm volatile("cp.async.wait_group 1;" ::: "memory");
        } else {
            asm volatile("cp.async.wait_group 0;" ::: "memory");
        }
        __syncthreads();

        // ---- S = (Q*scale) K^T ----
        float sa[8][4];
#pragma unroll
        for (int j = 0; j < 8; j++)
            sa[j][0] = sa[j][1] = sa[j][2] = sa[j][3] = 0.f;
        const uint32_t kb = Kaddr[bi] + krow_off;
#pragma unroll
        for (int kk = 0; kk < 8; kk++) {
#pragma unroll
            for (int jp = 0; jp < 4; jp++) {
                uint32_t t0, t1, t2, t3;
                ldsm4(t0, t1, t2, t3, kb + jp * 16 * KROWB + kk * 32);
                mma16(sa[2 * jp], qf[kk][0], qf[kk][1], qf[kk][2], qf[kk][3], t0, t1);
                mma16(sa[2 * jp + 1], qf[kk][0], qf[kk][1], qf[kk][2], qf[kk][3], t2, t3);
            }
        }

        // ---- p = exp(s) * sel ; pack to fp16 A-fragments (no shfl!) ----
        const int n0 = t * 64;
        uint32_t ph0[8], ph1[8];
#pragma unroll
        for (int j = 0; j < 8; j++) {
            float2 ms = *(const float2*)(sMask + n0 + j * 8 + 2 * tig);
            float p00 = __expf(sa[j][0]) * ms.x;
            float p01 = __expf(sa[j][1]) * ms.y;
            float p10 = __expf(sa[j][2]) * ms.x;
            float p11 = __expf(sa[j][3]) * ms.y;
            l0 += p00 + p01;
            l1 += p10 + p11;
            ph0[j] = f2h2(p00, p01);
            ph1[j] = f2h2(p10, p11);
        }

        // ---- O += P V ----
        const uint32_t vb = Vaddr[bi] + vrow_off;
#pragma unroll
        for (int kk = 0; kk < 4; kk++) {
            uint32_t a0 = ph0[2 * kk], a1 = ph1[2 * kk];
            uint32_t a2 = ph0[2 * kk + 1], a3 = ph1[2 * kk + 1];
#pragma unroll
            for (int np = 0; np < 8; np++) {
                uint32_t t0, t1, t2, t3;
                ldsm4(t0, t1, t2, t3, vb + np * 16 * VROWB + kk * 32);
                mma16(oa[2 * np], a0, a1, a2, a3, t0, t1);
                mma16(oa[2 * np + 1], a0, a1, a2, a3, t2, t3);
            }
        }
        __syncthreads();   // buffers consumed before next issue overwrites
    }

    // ---- epilogue: reduce l over quad, normalize, store ----
    l0 += __shfl_xor_sync(0xffffffffu, l0, 1);
    l0 += __shfl_xor_sync(0xffffffffu, l0, 2);
    l1 += __shfl_xor_sync(0xffffffffu, l1, 1);
    l1 += __shfl_xor_sync(0xffffffffu, l1, 2);
    float i0 = 1.f / l0, i1 = 1.f / l1;
    float* og = out + bh_base + (size_t)qb * BM * Dd;
#pragma unroll
    for (int n = 0; n < 16; n++) {
        int c = n * 8 + 2 * tig;
        *(float2*)(og + (size_t)r0 * Dd + c) = make_float2(oa[n][0] * i0, oa[n][1] * i0);
        *(float2*)(og + (size_t)r1 * Dd + c) = make_float2(oa[n][2] * i1, oa[n][3] * i1);
    }
}

extern "C" void kernel_launch(void* const* d_in, const int* in_sizes, int n_in,
                              void* d_out, int out_size) {
    (void)in_sizes; (void)n_in; (void)out_size;
    const float* q = (const float*)d_in[0];
    const float* k = (const float*)d_in[1];
    const float* v = (const float*)d_in[2];
    const int* mask = (const int*)d_in[3];
    float* out = (float*)d_out;

    compact_kernel<<<Bc, 256>>>(mask);
    prep_kernel<<<dim3(Ss / 64, Bc * Hh), 256>>>(k, v);

    constexpr int SMEM_BYTES = 2 * KTILEB + 2 * VTILEB + Ss * 4;  // 79872
    cudaFuncSetAttribute(fa_kernel, cudaFuncAttributeMaxDynamicSharedMemorySize,
                         SMEM_BYTES);
    fa_kernel<<<dim3(Ss / BM, Bc * Hh), NT, SMEM_BYTES>>>(q, out);
}

// round 8
// speedup vs baseline: 4.5696x; 1.1213x over previous
#include <cuda_runtime.h>
#include <cuda_fp16.h>
#include <cstdint>

// Problem: B=2, H=16, S=2048, D=128, fp32 in/out, int32 mask over keys.
// Masked keys (~50%) contribute exactly zero -> K/V compacted in prep (which
// recomputes the ballot-scan itself; no separate compact kernel). Padding
// slots are ZERO rows: p = exp(0) = 1 exactly, contributes 0 to O; the exact
// pad count is subtracted from l in the epilogue.
// fp16 datapath, m16n8k16, XOR-swizzled smem (no padding) -> 64KB/CTA -> 3 CTAs/SM.
constexpr int Bc = 2, Hh = 16, Ss = 2048, Dd = 128;
constexpr int BM = 64;          // queries per block (4 warps x 16 rows)
constexpr int NT = 128;         // threads
constexpr float SCALE_F = 0.08838834764831845f;  // 1/sqrt(128)

constexpr int KTILEB = 64 * 256;    // 16384 (64 keys x 128 fp16, swizzled rows)
constexpr int VTILEB = 128 * 128;   // 16384 (128 d-rows x 64 fp16 keys, swizzled)

// fp16 operands, compacted: g_kh [bh][j][d], g_vth [bh][d][j] (zeros at padding)
__device__ __align__(16) __half g_kh[(size_t)Bc * Hh * Ss * Dd];
__device__ __align__(16) __half g_vth[(size_t)Bc * Hh * Dd * Ss];

__device__ __forceinline__ uint32_t f2h2(float lo, float hi) {
    __half2 h = __floats2half2_rn(lo, hi);
    return *(uint32_t*)&h;
}

__device__ __forceinline__ void mma16(float* d, uint32_t a0, uint32_t a1, uint32_t a2,
                                      uint32_t a3, uint32_t b0, uint32_t b1) {
    asm volatile(
        "mma.sync.aligned.m16n8k16.row.col.f32.f16.f16.f32 "
        "{%0,%1,%2,%3},{%4,%5,%6,%7},{%8,%9},{%0,%1,%2,%3};"
        : "+f"(d[0]), "+f"(d[1]), "+f"(d[2]), "+f"(d[3])
        : "r"(a0), "r"(a1), "r"(a2), "r"(a3), "r"(b0), "r"(b1));
}

__device__ __forceinline__ void ldsm4(uint32_t& t0, uint32_t& t1, uint32_t& t2,
                                      uint32_t& t3, uint32_t addr) {
    asm volatile("ldmatrix.sync.aligned.m8n8.x4.shared.b16 {%0,%1,%2,%3}, [%4];"
                 : "=r"(t0), "=r"(t1), "=r"(t2), "=r"(t3) : "r"(addr));
}

__device__ __forceinline__ void cp16(uint32_t dst, const void* src) {
    asm volatile("cp.async.ca.shared.global [%0], [%1], 16;" :: "r"(dst), "l"(src));
}
#define CP_COMMIT() asm volatile("cp.async.commit_group;" ::: "memory")

// ---------------- prep: scan (recomputed per block) + gather + fp16 convert ----
__global__ void __launch_bounds__(256) prep_kernel(const float* __restrict__ k,
                                                   const float* __restrict__ v,
                                                   const int* __restrict__ mask) {
    __shared__ float sv[64 * 129];
    __shared__ int wcnt[64], woff[64];
    __shared__ int sidx[64];
    __shared__ int s_ntrue;
    const int t = blockIdx.x, bh = blockIdx.y, tid = threadIdx.x;
    const int b = bh >> 4;
    const int warp = tid >> 5, lane = tid & 31;

    // per-32-chunk mask counts
    for (int ch = warp; ch < 64; ch += 8) {
        int m = mask[b * Ss + ch * 32 + lane] != 0;
        unsigned bal = __ballot_sync(0xffffffffu, m);
        if (lane == 0) wcnt[ch] = __popc(bal);
    }
    __syncthreads();
    if (tid == 0) {
        int s = 0;
        for (int i = 0; i < 64; i++) { woff[i] = s; s += wcnt[i]; }
        s_ntrue = s;
    }
    __syncthreads();
    const int ntrue = s_ntrue;
    const int npad = (ntrue + 63) & ~63;
    if (t * 64 >= npad) return;
    const int base = t * 64;

    if (tid < 64) sidx[tid] = -1;   // -1 => zero padding row
    __syncthreads();
    for (int ch = warp; ch < 64; ch += 8) {
        int src = ch * 32 + lane;
        int m = mask[b * Ss + src] != 0;
        unsigned bal = __ballot_sync(0xffffffffu, m);
        if (m) {
            int pos = woff[ch] + __popc(bal & ((1u << lane) - 1u));
            if (pos >= base && pos < base + 64) sidx[pos - base] = src;
        }
    }
    __syncthreads();

    const float* kg = k + (size_t)bh * Ss * Dd;
    const float* vg = v + (size_t)bh * Ss * Dd;

    // K: gather rows (zeros for padding), convert to fp16
    uint32_t* ko = (uint32_t*)(g_kh + ((size_t)bh * Ss + base) * Dd);
    for (int i = tid; i < 64 * 32; i += 256) {
        int r = i >> 5, c4 = (i & 31) << 2;
        int idx = sidx[r];
        float4 x = (idx >= 0) ? *(const float4*)(kg + (size_t)idx * Dd + c4)
                              : make_float4(0.f, 0.f, 0.f, 0.f);
        ko[(r * Dd + c4) >> 1] = f2h2(x.x, x.y);
        ko[((r * Dd + c4) >> 1) + 1] = f2h2(x.z, x.w);
    }

    // V: gather rows into smem fp32 (zeros for padding), then transposed fp16
    for (int i = tid; i < 64 * 32; i += 256) {
        int r = i >> 5, c4 = (i & 31) << 2;
        int idx = sidx[r];
        float4 x = (idx >= 0) ? *(const float4*)(vg + (size_t)idx * Dd + c4)
                              : make_float4(0.f, 0.f, 0.f, 0.f);
        sv[r * 129 + c4 + 0] = x.x; sv[r * 129 + c4 + 1] = x.y;
        sv[r * 129 + c4 + 2] = x.z; sv[r * 129 + c4 + 3] = x.w;
    }
    __syncthreads();
    uint32_t* vo = (uint32_t*)(g_vth + (size_t)bh * Dd * Ss);
    for (int i = tid; i < 128 * 32; i += 256) {
        int d = i >> 5, kp = i & 31;
        uint32_t h = f2h2(sv[(2 * kp) * 129 + d], sv[(2 * kp + 1) * 129 + d]);
        vo[((size_t)d * Ss + base) / 2 + kp] = h;
    }
}

// ---------------- main kernel ----------------
// dyn smem: K0 16K | K1 16K | V0 16K | V1 16K = 64KB -> 3 CTAs/SM
__global__ void __launch_bounds__(NT, 3)
fa_kernel(const float* __restrict__ q, const int* __restrict__ mask,
          float* __restrict__ out) {
    extern __shared__ char sm[];
    __shared__ int red[4];
    const uint32_t sbase = (uint32_t)__cvta_generic_to_shared(sm);
    const uint32_t Kaddr[2] = {sbase, sbase + KTILEB};
    const uint32_t Vaddr[2] = {sbase + 2u * KTILEB, sbase + 2u * KTILEB + VTILEB};

    const int tid = threadIdx.x, warp = tid >> 5, lane = tid & 31;
    const int g = lane >> 2, tig = lane & 3;
    const int qb = blockIdx.x, bh = blockIdx.y, b = bh >> 4;  // Hh=16
    const size_t bh_base = (size_t)bh * Ss * Dd;

    // count unmasked keys (mask is 8KB, L2-hot)
    int cnt = 0;
    for (int i = tid; i < Ss; i += NT) cnt += (mask[b * Ss + i] != 0);
#pragma unroll
    for (int s = 16; s > 0; s >>= 1) cnt += __shfl_xor_sync(0xffffffffu, cnt, s);
    if (lane == 0) red[warp] = cnt;
    __syncthreads();
    const int ntrue = red[0] + red[1] + red[2] + red[3];
    const int ntiles = (ntrue + 63) >> 6;
    const float padf = (float)(ntiles * 64 - ntrue);

    // Q fragments straight from global (one-time, pre-scaled fp16)
    const float* qg = q + bh_base + (size_t)qb * BM * Dd;
    const int r0 = warp * 16 + g, r1 = r0 + 8;
    uint32_t qf[8][4];
#pragma unroll
    for (int kk = 0; kk < 8; kk++) {
        float2 a = *(const float2*)(qg + (size_t)r0 * Dd + kk * 16 + 2 * tig);
        float2 bq = *(const float2*)(qg + (size_t)r1 * Dd + kk * 16 + 2 * tig);
        float2 c = *(const float2*)(qg + (size_t)r0 * Dd + kk * 16 + 2 * tig + 8);
        float2 d = *(const float2*)(qg + (size_t)r1 * Dd + kk * 16 + 2 * tig + 8);
        qf[kk][0] = f2h2(a.x * SCALE_F, a.y * SCALE_F);
        qf[kk][1] = f2h2(bq.x * SCALE_F, bq.y * SCALE_F);
        qf[kk][2] = f2h2(c.x * SCALE_F, c.y * SCALE_F);
        qf[kk][3] = f2h2(d.x * SCALE_F, d.y * SCALE_F);
    }

    const __half* ksrc = g_kh + (size_t)bh * Ss * Dd;
    const __half* vsrc = g_vth + (size_t)bh * Dd * Ss;

    auto issue_tile = [&](int t, int bi) {
        const __half* ks = ksrc + (size_t)t * 64 * Dd;
#pragma unroll
        for (int i = 0; i < 8; i++) {          // K: 64 rows x 16 chunks of 16B
            int ch = tid + i * NT;
            int r = ch >> 4, c = ch & 15;
            cp16(Kaddr[bi] + r * 256 + ((c ^ (r & 7)) << 4), ks + r * Dd + c * 8);
        }
        const __half* vs = vsrc + (size_t)t * 64;
#pragma unroll
        for (int i = 0; i < 8; i++) {          // VT: 128 rows x 8 chunks of 16B
            int ch = tid + i * NT;
            int r = ch >> 3, c = ch & 7;
            cp16(Vaddr[bi] + r * 128 + ((c ^ (r & 7)) << 4), vs + (size_t)r * Ss + c * 8);
        }
        CP_COMMIT();
    };

    // ldmatrix lane addressing (x4): lanes 0-7 mat0, 8-15 mat1, 16-23 mat2, 24-31 mat3
    const int mi = lane >> 3, mrow = lane & 7;
    const uint32_t krow = (uint32_t)((8 * (mi >> 1) + mrow) * 256);
    const uint32_t vrow = (uint32_t)((8 * (mi >> 1) + mrow) * 128);
    const int cbase = mi & 1;   // chunk low bit

    float oa[16][4];
#pragma unroll
    for (int n = 0; n < 16; n++)
        oa[n][0] = oa[n][1] = oa[n][2] = oa[n][3] = 0.f;
    float l0 = 0.f, l1 = 0.f;

    issue_tile(0, 0);

#pragma unroll 1
    for (int t = 0; t < ntiles; t++) {
        const int bi = t & 1;
        asm volatile("cp.async.wait_group 0;" ::: "memory");
        __syncthreads();             // tile t visible; all warps done with bi^1
        if (t + 1 < ntiles) issue_tile(t + 1, bi ^ 1);

        // ---- S = (Q*scale) K^T ----
        float sa[8][4];
#pragma unroll
        for (int j = 0; j < 8; j++)
            sa[j][0] = sa[j][1] = sa[j][2] = sa[j][3] = 0.f;
        const uint32_t kb = Kaddr[bi] + krow;
#pragma unroll
        for (int kk = 0; kk < 8; kk++) {
            const uint32_t kch = (uint32_t)(((kk * 2 + cbase) ^ mrow) << 4);
#pragma unroll
            for (int jp = 0; jp < 4; jp++) {
                uint32_t t0, t1, t2, t3;
                ldsm4(t0, t1, t2, t3, kb + jp * 4096 + kch);
                mma16(sa[2 * jp], qf[kk][0], qf[kk][1], qf[kk][2], qf[kk][3], t0, t1);
                mma16(sa[2 * jp + 1], qf[kk][0], qf[kk][1], qf[kk][2], qf[kk][3], t2, t3);
            }
        }

        // ---- p = exp(s) (padding rows are zero -> p = 1, fixed in epilogue) ----
        uint32_t ph0[8], ph1[8];
#pragma unroll
        for (int j = 0; j < 8; j++) {
            float p00 = __expf(sa[j][0]);
            float p01 = __expf(sa[j][1]);
            float p10 = __expf(sa[j][2]);
            float p11 = __expf(sa[j][3]);
            l0 += p00 + p01;
            l1 += p10 + p11;
            ph0[j] = f2h2(p00, p01);
            ph1[j] = f2h2(p10, p11);
        }

        // ---- O += P V ----
        const uint32_t vb = Vaddr[bi] + vrow;
#pragma unroll
        for (int kk = 0; kk < 4; kk++) {
            uint32_t a0 = ph0[2 * kk], a1 = ph1[2 * kk];
            uint32_t a2 = ph0[2 * kk + 1], a3 = ph1[2 * kk + 1];
            const uint32_t vch = (uint32_t)(((kk * 2 + cbase) ^ mrow) << 4);
#pragma unroll
            for (int np = 0; np < 8; np++) {
                uint32_t t0, t1, t2, t3;
                ldsm4(t0, t1, t2, t3, vb + np * 2048 + vch);
                mma16(oa[2 * np], a0, a1, a2, a3, t0, t1);
                mma16(oa[2 * np + 1], a0, a1, a2, a3, t2, t3);
            }
        }
    }

    // ---- epilogue: quad-reduce l, subtract exact padding count, store ----
    l0 += __shfl_xor_sync(0xffffffffu, l0, 1);
    l0 += __shfl_xor_sync(0xffffffffu, l0, 2);
    l1 += __shfl_xor_sync(0xffffffffu, l1, 1);
    l1 += __shfl_xor_sync(0xffffffffu, l1, 2);
    float i0 = 1.f / (l0 - padf), i1 = 1.f / (l1 - padf);
    float* og = out + bh_base + (size_t)qb * BM * Dd;
#pragma unroll
    for (int n = 0; n < 16; n++) {
        int c = n * 8 + 2 * tig;
        *(float2*)(og + (size_t)r0 * Dd + c) = make_float2(oa[n][0] * i0, oa[n][1] * i0);
        *(float2*)(og + (size_t)r1 * Dd + c) = make_float2(oa[n][2] * i1, oa[n][3] * i1);
    }
}

extern "C" void kernel_launch(void* const* d_in, const int* in_sizes, int n_in,
                              void* d_out, int out_size) {
    (void)in_sizes; (void)n_in; (void)out_size;
    const float* q = (const float*)d_in[0];
    const float* k = (const float*)d_in[1];
    const float* v = (const float*)d_in[2];
    const int* mask = (const int*)d_in[3];
    float* out = (float*)d_out;

    prep_kernel<<<dim3(Ss / 64, Bc * Hh), 256>>>(k, v, mask);

    constexpr int SMEM_BYTES = 2 * KTILEB + 2 * VTILEB;  // 65536
    cudaFuncSetAttribute(fa_kernel, cudaFuncAttributeMaxDynamicSharedMemorySize,
                         SMEM_BYTES);
    fa_kernel<<<dim3(Ss / BM, Bc * Hh), NT, SMEM_BYTES>>>(q, mask, out);
}